// round 15
// baseline (speedup 1.0000x reference)
#include <cuda_runtime.h>
#include <cuda_bf16.h>
#include <math.h>
#include <stdint.h>

// ---------------------------------------------------------------------------
// TrajectoryGAT: 2x GATConv + mean pool + linear + log_softmax
//   N=100000, E=1600000/layer, HID=128, G=256, OUT=2
//
// R15 changes vs R14 (288.8us):
//   - aggregate serial loop processes 2 edges/iteration: lanes 0-15 handle
//     edge t, lanes 16-31 edge t+1; each lane owns 8 channels via one
//     LDG.128 (8 x bf16). Parallel exp phase + SHFL broadcast retained
//     (the R8 regression came from per-lane scalar broadcast loads — avoided).
//   - cross-half combine: 8 shfl-xor-16 per node (amortized over ~16 edges)
// ---------------------------------------------------------------------------

#define NN 100000
#define EE 1600000
#define HID 128
#define SCAN_ELEMS 2048

// ---- device scratch ----
__device__ __align__(16) uint2    g_hb[(size_t)NN * 32];    // h (bf16) gathers
__device__ __align__(16) uint2    g_ab[(size_t)NN * 32];    // layer-1 out bf16 = GEMM A
__device__ __align__(16) float    g_acc[(size_t)NN * HID];  // layer-2 out fp32
__device__ float    g_as[NN];
__device__ float    g_ad[NN];
__device__ __align__(16) int g_cnt[2 * NN];
__device__ int      g_rowc[2 * NN + 1];
__device__ int      g_cur[2 * NN];
__device__ int      g_csrc[2 * EE];
__device__ __align__(16) unsigned g_w2b[64 * HID];          // W2 bf16x2 [k][n]
// lookback state (zero at entry; scatter re-zeroes)
__device__ int      g_ticket;
__device__ int      g_bflag[128];
__device__ int      g_bagg[128];
__device__ int      g_binc[128];

__device__ __forceinline__ uint2 pack4bf(float a, float b, float c, float d) {
    uint2 r;
    __nv_bfloat162 p0 = __float22bfloat162_rn(make_float2(a, b));
    __nv_bfloat162 p1 = __float22bfloat162_rn(make_float2(c, d));
    r.x = *(unsigned*)&p0;
    r.y = *(unsigned*)&p1;
    return r;
}

__device__ __forceinline__ float4 unpack4bf(uint2 v) {
    float2 f0 = __bfloat1622float2(*(__nv_bfloat162*)&v.x);
    float2 f1 = __bfloat1622float2(*(__nv_bfloat162*)&v.y);
    return make_float4(f0.x, f0.y, f1.x, f1.y);
}

// ---------------------------------------------------------------------------
// Fused: layer-1 transform (+ dots + W2 convert) || both histograms.
__global__ void transform_hist_kernel(const float* __restrict__ x, const float* __restrict__ W,
                                      const float* __restrict__ atts, const float* __restrict__ attd,
                                      const int* __restrict__ dst_s, const int* __restrict__ dst_t,
                                      const float* __restrict__ W2, int N, int E, int TB) {
    if ((int)blockIdx.x < TB) {
        int gid = blockIdx.x * 256 + threadIdx.x;
        if (gid < 64 * HID) {
            float2 v = *(const float2*)(W2 + gid * 2);
            __nv_bfloat162 p = __float22bfloat162_rn(v);
            g_w2b[gid] = *(unsigned*)&p;
        }
        int node = gid >> 5;
        int lane = threadIdx.x & 31;
        if (node >= N) return;
        float xv = (lane < 9) ? x[(size_t)node * 9 + lane] : 0.f;
        float4 acc = make_float4(0.f, 0.f, 0.f, 0.f);
#pragma unroll
        for (int k = 0; k < 9; k++) {
            float xk = __shfl_sync(0xffffffffu, xv, k);
            float4 w = *(const float4*)(W + k * HID + lane * 4);
            acc.x = fmaf(xk, w.x, acc.x);
            acc.y = fmaf(xk, w.y, acc.y);
            acc.z = fmaf(xk, w.z, acc.z);
            acc.w = fmaf(xk, w.w, acc.w);
        }
        g_hb[(size_t)node * 32 + lane] = pack4bf(acc.x, acc.y, acc.z, acc.w);
        float4 s4 = *(const float4*)(atts + lane * 4);
        float4 d4 = *(const float4*)(attd + lane * 4);
        float ps = acc.x * s4.x + acc.y * s4.y + acc.z * s4.z + acc.w * s4.w;
        float pd = acc.x * d4.x + acc.y * d4.y + acc.z * d4.z + acc.w * d4.w;
#pragma unroll
        for (int off = 16; off >= 1; off >>= 1) {
            ps += __shfl_xor_sync(0xffffffffu, ps, off);
            pd += __shfl_xor_sync(0xffffffffu, pd, off);
        }
        if (lane == 0) { g_as[node] = ps; g_ad[node] = pd; }
    } else {
        int ES4 = (E + 3) >> 2;
        int idx = (blockIdx.x - TB) * 256 + threadIdx.x;
        const int* dsa;
        int base, off0;
        if (idx < ES4)          { dsa = dst_s; base = idx * 4;         off0 = 0; }
        else if (idx < 2 * ES4) { dsa = dst_t; base = (idx - ES4) * 4; off0 = NN; }
        else return;
        if (base + 3 < E) {
            int4 d = *(const int4*)(dsa + base);
            atomicAdd(&g_cnt[off0 + d.x], 1);
            atomicAdd(&g_cnt[off0 + d.y], 1);
            atomicAdd(&g_cnt[off0 + d.z], 1);
            atomicAdd(&g_cnt[off0 + d.w], 1);
        } else {
            for (int j = base; j < E; ++j) atomicAdd(&g_cnt[off0 + dsa[j]], 1);
        }
    }
}

// ---------------------------------------------------------------------------
// Single-pass decoupled-lookback exclusive scan.
__global__ __launch_bounds__(1024) void scan_kernel(int n2, int nb) {
    __shared__ int sbid_sh, s_total, s_prefix;
    __shared__ int ws[32];
    int t = threadIdx.x, lane = t & 31, w = t >> 5;
    if (t == 0) sbid_sh = atomicAdd(&g_ticket, 1);
    __syncthreads();
    int bid = sbid_sh;
    int base = bid * SCAN_ELEMS;
    int i0 = base + t * 2;
    int2 v = make_int2(0, 0);
    if (i0 + 1 < n2) v = *(const int2*)&g_cnt[i0];
    else if (i0 < n2) v.x = g_cnt[i0];
    int local = v.x + v.y;
    int xv = local;
#pragma unroll
    for (int off = 1; off < 32; off <<= 1) {
        int u = __shfl_up_sync(0xffffffffu, xv, off);
        if (lane >= off) xv += u;
    }
    if (lane == 31) ws[w] = xv;
    __syncthreads();
    if (w == 0) {
        int s = ws[lane];
        int y = s;
#pragma unroll
        for (int off = 1; off < 32; off <<= 1) {
            int u = __shfl_up_sync(0xffffffffu, y, off);
            if (lane >= off) y += u;
        }
        ws[lane] = y - s;
        if (lane == 31) s_total = y;
    }
    __syncthreads();
    int thr_incl = xv + ws[w];
    int btotal = s_total;

    if (t == 0) {
        if (bid == 0) {
            g_binc[0] = btotal;
            __threadfence();
            atomicExch(&g_bflag[0], 2);
        } else {
            g_bagg[bid] = btotal;
            __threadfence();
            atomicExch(&g_bflag[bid], 1);
        }
    }
    if (t < 32) {
        int pre = 0;
        if (bid > 0) {
            int jbase = bid - 1;
            while (true) {
                int j = jbase - lane;
                int f = 0;
                if (j >= 0) {
                    do { f = atomicAdd(&g_bflag[j], 0); } while (f == 0);
                }
                int val = 0;
                if (j >= 0)
                    val = (f == 2) ? atomicAdd(&g_binc[j], 0) : atomicAdd(&g_bagg[j], 0);
                unsigned pm = __ballot_sync(0xffffffffu, j >= 0 && f == 2);
                if (pm) {
                    int fp = __ffs(pm) - 1;
                    int contrib = (lane <= fp) ? val : 0;
#pragma unroll
                    for (int off = 16; off >= 1; off >>= 1)
                        contrib += __shfl_xor_sync(0xffffffffu, contrib, off);
                    pre += contrib;
                    break;
                } else {
                    int contrib = val;
#pragma unroll
                    for (int off = 16; off >= 1; off >>= 1)
                        contrib += __shfl_xor_sync(0xffffffffu, contrib, off);
                    pre += contrib;
                    jbase -= 32;
                }
            }
            if (lane == 0) {
                g_binc[bid] = pre + btotal;
                __threadfence();
                atomicExch(&g_bflag[bid], 2);
            }
        }
        if (lane == 0) s_prefix = pre;
    }
    __syncthreads();
    int pfx = s_prefix;
    int excl = pfx + thr_incl - local;
    if (i0 < n2) { g_rowc[i0] = excl; g_cur[i0] = excl; }
    if (i0 + 1 < n2) { g_rowc[i0 + 1] = excl + v.x; g_cur[i0 + 1] = excl + v.x; }
    if (bid == nb - 1 && t == 0) g_rowc[n2] = pfx + btotal;
}

// ---------------------------------------------------------------------------
// Both scatters in one launch + state reset for next graph replay.
__global__ void scatter_kernel(const int* __restrict__ src_s, const int* __restrict__ dst_s,
                               const int* __restrict__ src_t, const int* __restrict__ dst_t,
                               int E, int n2) {
    int i = blockIdx.x * 256 + threadIdx.x;
    if (i < E) {
        int p = atomicAdd(&g_cur[dst_s[i]], 1);
        g_csrc[p] = src_s[i];
    } else if (i < 2 * E) {
        int k = i - E;
        int p = atomicAdd(&g_cur[NN + dst_t[k]], 1);
        g_csrc[p] = src_t[k];
    }
    if (i < n2) g_cnt[i] = 0;
    if (i < 128) g_bflag[i] = 0;
    if (i == 0) g_ticket = 0;
}

// ---------------------------------------------------------------------------
// Aggregation: one warp/dst, single pass (m=0 softmax). Parallel phase
// computes (src, w=exp(alpha)) for 32 edges; serial loop does 2 edges/iter:
// lanes 0-15 edge t, lanes 16-31 edge t+1, 8 channels/lane via LDG.128.
template <int LAYER>
__global__ __launch_bounds__(256, 6) void aggregate_kernel(const float* __restrict__ bias, int n) {
    int node = (blockIdx.x * blockDim.x + threadIdx.x) >> 5;
    int lane = threadIdx.x & 31;
    if (node >= n) return;
    const int* rowb = g_rowc + LAYER * NN;
    int start = rowb[node], end = rowb[node + 1];
    int sub = lane & 15, half = lane >> 4;
    float4 b0 = *(const float4*)(bias + sub * 8);
    float4 b1 = *(const float4*)(bias + sub * 8 + 4);

    if (start == end) {
        if (half == 0) {
            if (LAYER == 0) {
                float4 o0 = b0, o1 = b1;
                o0.x = fmaxf(o0.x, 0.f); o0.y = fmaxf(o0.y, 0.f);
                o0.z = fmaxf(o0.z, 0.f); o0.w = fmaxf(o0.w, 0.f);
                o1.x = fmaxf(o1.x, 0.f); o1.y = fmaxf(o1.y, 0.f);
                o1.z = fmaxf(o1.z, 0.f); o1.w = fmaxf(o1.w, 0.f);
                uint2 p0 = pack4bf(o0.x, o0.y, o0.z, o0.w);
                uint2 p1 = pack4bf(o1.x, o1.y, o1.z, o1.w);
                *(uint4*)((unsigned*)g_ab + (size_t)node * 64 + sub * 4) =
                    make_uint4(p0.x, p0.y, p1.x, p1.y);
            } else {
                *(float4*)(g_acc + (size_t)node * HID + sub * 8) = b0;
                *(float4*)(g_acc + (size_t)node * HID + sub * 8 + 4) = b1;
            }
        }
        return;
    }

    float ad = g_ad[node];
    float ssum = 0.f;
    float c0 = 0.f, c1 = 0.f, c2 = 0.f, c3 = 0.f;
    float c4 = 0.f, c5 = 0.f, c6 = 0.f, c7 = 0.f;
    const char* hbase = (const char*)g_hb + sub * 16;
    for (int basei = start; basei < end; basei += 32) {
        int nloc = min(32, end - basei);
        int srcl = 0;
        float wv = 0.f;
        if (lane < nloc) {
            srcl = g_csrc[basei + lane];
            float a = g_as[srcl] + ad;
            a = fmaxf(a, 0.2f * a);          // leaky_relu(., 0.2)
            wv = __expf(fminf(a, 80.f));     // m=0; clamp guards overflow
        }
        ssum += wv;                          // each edge counted once per warp
#pragma unroll 4
        for (int t = 0; t < nloc; t += 2) {
            int sl = t + half;               // <= 31 always
            int sidx = __shfl_sync(0xffffffffu, srcl, sl);
            float wt = __shfl_sync(0xffffffffu, wv, sl);
            // lanes beyond nloc hold wv=0, src=0 -> odd-tail half contributes 0
            uint4 hv4 = *(const uint4*)(hbase + (size_t)sidx * 256);
            float4 hA = unpack4bf(make_uint2(hv4.x, hv4.y));
            float4 hB = unpack4bf(make_uint2(hv4.z, hv4.w));
            c0 = fmaf(wt, hA.x, c0);
            c1 = fmaf(wt, hA.y, c1);
            c2 = fmaf(wt, hA.z, c2);
            c3 = fmaf(wt, hA.w, c3);
            c4 = fmaf(wt, hB.x, c4);
            c5 = fmaf(wt, hB.y, c5);
            c6 = fmaf(wt, hB.z, c6);
            c7 = fmaf(wt, hB.w, c7);
        }
    }
    // combine halves (lane L in [0,16) pairs with L+16, same channels)
    c0 += __shfl_xor_sync(0xffffffffu, c0, 16);
    c1 += __shfl_xor_sync(0xffffffffu, c1, 16);
    c2 += __shfl_xor_sync(0xffffffffu, c2, 16);
    c3 += __shfl_xor_sync(0xffffffffu, c3, 16);
    c4 += __shfl_xor_sync(0xffffffffu, c4, 16);
    c5 += __shfl_xor_sync(0xffffffffu, c5, 16);
    c6 += __shfl_xor_sync(0xffffffffu, c6, 16);
    c7 += __shfl_xor_sync(0xffffffffu, c7, 16);
#pragma unroll
    for (int off = 16; off >= 1; off >>= 1)
        ssum += __shfl_xor_sync(0xffffffffu, ssum, off);

    if (half == 0) {
        float inv = 1.f / (ssum + 1e-16f);
        float o0 = fmaf(c0, inv, b0.x), o1 = fmaf(c1, inv, b0.y);
        float o2 = fmaf(c2, inv, b0.z), o3 = fmaf(c3, inv, b0.w);
        float o4 = fmaf(c4, inv, b1.x), o5 = fmaf(c5, inv, b1.y);
        float o6 = fmaf(c6, inv, b1.z), o7 = fmaf(c7, inv, b1.w);
        if (LAYER == 0) {
            o0 = fmaxf(o0, 0.f); o1 = fmaxf(o1, 0.f);
            o2 = fmaxf(o2, 0.f); o3 = fmaxf(o3, 0.f);
            o4 = fmaxf(o4, 0.f); o5 = fmaxf(o5, 0.f);
            o6 = fmaxf(o6, 0.f); o7 = fmaxf(o7, 0.f);
            uint2 p0 = pack4bf(o0, o1, o2, o3);
            uint2 p1 = pack4bf(o4, o5, o6, o7);
            *(uint4*)((unsigned*)g_ab + (size_t)node * 64 + sub * 4) =
                make_uint4(p0.x, p0.y, p1.x, p1.y);
        } else {
            *(float4*)(g_acc + (size_t)node * HID + sub * 8) = make_float4(o0, o1, o2, o3);
            *(float4*)(g_acc + (size_t)node * HID + sub * 8 + 4) = make_float4(o4, o5, o6, o7);
        }
    }
}

// ---------------------------------------------------------------------------
// Tensor-core GEMM: h2[M,128] = g_ab(bf16) @ g_w2b, fp32 accum.
// Epilogue: bf16 store to g_hb + fused attention dots.
__global__ __launch_bounds__(256) void gemm_mma_kernel(const float* __restrict__ atts,
                                                       const float* __restrict__ attd, int M) {
    __shared__ __nv_bfloat16 As[128 * 72];
    __shared__ __nv_bfloat16 Bs[64 * 136];
    int tid = threadIdx.x;
    int lane = tid & 31, w = tid >> 5;
    int m0 = blockIdx.x * 128;
    float c[16][4];
#pragma unroll
    for (int i = 0; i < 16; i++)
#pragma unroll
        for (int j = 0; j < 4; j++) c[i][j] = 0.f;

    const char* abase = (const char*)g_ab;
    const char* bbase = (const char*)g_w2b;
    int grp = lane >> 3;
    int mw = w * 16;

    for (int ks = 0; ks < 2; ++ks) {
#pragma unroll
        for (int it = 0; it < 4; ++it) {
            int idx = tid + it * 256;
            int r = idx >> 3, c8 = idx & 7;
            uint4 v = make_uint4(0, 0, 0, 0);
            if (m0 + r < M)
                v = *(const uint4*)(abase + (size_t)(m0 + r) * 256 + ks * 128 + c8 * 16);
            *(uint4*)((char*)As + r * 144 + c8 * 16) = v;
        }
#pragma unroll
        for (int it = 0; it < 4; ++it) {
            int idx = tid + it * 256;
            int r = idx >> 4, c16 = idx & 15;
            uint4 v = *(const uint4*)(bbase + (size_t)(ks * 64 + r) * 256 + c16 * 16);
            *(uint4*)((char*)Bs + r * 272 + c16 * 16) = v;
        }
        __syncthreads();

#pragma unroll
        for (int kk = 0; kk < 64; kk += 16) {
            int arow = mw + (lane & 7) + (grp & 1) * 8;
            int acol = kk + (grp >> 1) * 8;
            uint32_t aaddr = (uint32_t)__cvta_generic_to_shared(As) + arow * 144 + acol * 2;
            uint32_t a0, a1, a2, a3;
            asm volatile("ldmatrix.sync.aligned.m8n8.x4.shared.b16 {%0,%1,%2,%3}, [%4];"
                         : "=r"(a0), "=r"(a1), "=r"(a2), "=r"(a3) : "r"(aaddr));
#pragma unroll
            for (int np = 0; np < 8; ++np) {
                int brow = kk + (lane & 7) + (grp & 1) * 8;
                int bcol = np * 16 + (grp >> 1) * 8;
                uint32_t baddr = (uint32_t)__cvta_generic_to_shared(Bs) + brow * 272 + bcol * 2;
                uint32_t b0, b1, b2, b3;
                asm volatile("ldmatrix.sync.aligned.m8n8.x4.trans.shared.b16 {%0,%1,%2,%3}, [%4];"
                             : "=r"(b0), "=r"(b1), "=r"(b2), "=r"(b3) : "r"(baddr));
                asm volatile("mma.sync.aligned.m16n8k16.row.col.f32.bf16.bf16.f32 "
                             "{%0,%1,%2,%3}, {%4,%5,%6,%7}, {%8,%9}, {%0,%1,%2,%3};"
                             : "+f"(c[2 * np][0]), "+f"(c[2 * np][1]),
                               "+f"(c[2 * np][2]), "+f"(c[2 * np][3])
                             : "r"(a0), "r"(a1), "r"(a2), "r"(a3), "r"(b0), "r"(b1));
                asm volatile("mma.sync.aligned.m16n8k16.row.col.f32.bf16.bf16.f32 "
                             "{%0,%1,%2,%3}, {%4,%5,%6,%7}, {%8,%9}, {%0,%1,%2,%3};"
                             : "+f"(c[2 * np + 1][0]), "+f"(c[2 * np + 1][1]),
                               "+f"(c[2 * np + 1][2]), "+f"(c[2 * np + 1][3])
                             : "r"(a0), "r"(a1), "r"(a2), "r"(a3), "r"(b2), "r"(b3));
            }
        }
        __syncthreads();
    }

    int r = lane >> 2, q = lane & 3;
    int row1 = m0 + mw + r, row2 = row1 + 8;
    unsigned* hb32 = (unsigned*)g_hb;
    float ps1 = 0.f, pd1 = 0.f, ps2 = 0.f, pd2 = 0.f;
#pragma unroll
    for (int nt = 0; nt < 16; ++nt) {
        int col = nt * 8 + q * 2;
        float2 sa = *(const float2*)(atts + col);
        float2 da = *(const float2*)(attd + col);
        ps1 += c[nt][0] * sa.x + c[nt][1] * sa.y;
        pd1 += c[nt][0] * da.x + c[nt][1] * da.y;
        ps2 += c[nt][2] * sa.x + c[nt][3] * sa.y;
        pd2 += c[nt][2] * da.x + c[nt][3] * da.y;
        if (row1 < M) {
            __nv_bfloat162 p = __float22bfloat162_rn(make_float2(c[nt][0], c[nt][1]));
            hb32[(size_t)row1 * 64 + nt * 4 + q] = *(unsigned*)&p;
        }
        if (row2 < M) {
            __nv_bfloat162 p = __float22bfloat162_rn(make_float2(c[nt][2], c[nt][3]));
            hb32[(size_t)row2 * 64 + nt * 4 + q] = *(unsigned*)&p;
        }
    }
#pragma unroll
    for (int off = 1; off <= 2; off <<= 1) {
        ps1 += __shfl_xor_sync(0xffffffffu, ps1, off);
        pd1 += __shfl_xor_sync(0xffffffffu, pd1, off);
        ps2 += __shfl_xor_sync(0xffffffffu, ps2, off);
        pd2 += __shfl_xor_sync(0xffffffffu, pd2, off);
    }
    if (q == 0) {
        if (row1 < M) { g_as[row1] = ps1; g_ad[row1] = pd1; }
        if (row2 < M) { g_as[row2] = ps2; g_ad[row2] = pd2; }
    }
}

// ---------------------------------------------------------------------------
__global__ __launch_bounds__(512) void pool_kernel(const int* __restrict__ batch,
                                                   const float* __restrict__ Wc,
                                                   const float* __restrict__ bc,
                                                   float* __restrict__ out, int N) {
    int g = blockIdx.x;
    int t = threadIdx.x;
    int c = t & 127;
    int part = t >> 7;
    int lo = 0, hi = N;
    while (lo < hi) { int mid = (lo + hi) >> 1; if (batch[mid] < g) lo = mid + 1; else hi = mid; }
    int start = lo;
    hi = N;
    while (lo < hi) { int mid = (lo + hi) >> 1; if (batch[mid] < g + 1) lo = mid + 1; else hi = mid; }
    int end = lo;

    float sum = 0.f;
    for (int nd = start + part; nd < end; nd += 4) sum += g_acc[(size_t)nd * HID + c];
    __shared__ float sh[512];
    sh[t] = sum;
    __syncthreads();
    if (t < 128) {
        float s = sh[t] + sh[t + 128] + sh[t + 256] + sh[t + 384];
        float cnt = (float)(end - start);
        if (cnt < 1.f) cnt = 1.f;
        float p = s / cnt;
        sh[t] = p * Wc[c * 2 + 0];
        sh[t + 128] = p * Wc[c * 2 + 1];
    }
    __syncthreads();
    for (int off = 64; off >= 1; off >>= 1) {
        if (t < off) { sh[t] += sh[t + off]; sh[128 + t] += sh[128 + t + off]; }
        __syncthreads();
    }
    if (t == 0) {
        float l0 = sh[0] + bc[0];
        float l1 = sh[128] + bc[1];
        float mx = fmaxf(l0, l1);
        float lse = mx + logf(expf(l0 - mx) + expf(l1 - mx));
        out[g * 2 + 0] = l0 - lse;
        out[g * 2 + 1] = l1 - lse;
    }
}

// ---------------------------------------------------------------------------
extern "C" void kernel_launch(void* const* d_in, const int* in_sizes, int n_in,
                              void* d_out, int out_size) {
    const float* x      = (const float*)d_in[0];
    const int*   ei_s   = (const int*)d_in[1];
    const int*   ei_t   = (const int*)d_in[3];
    const int*   batch  = (const int*)d_in[5];
    const float* W1     = (const float*)d_in[6];
    const float* atts1  = (const float*)d_in[7];
    const float* attd1  = (const float*)d_in[8];
    const float* b1     = (const float*)d_in[9];
    const float* W2     = (const float*)d_in[10];
    const float* atts2  = (const float*)d_in[11];
    const float* attd2  = (const float*)d_in[12];
    const float* b2     = (const float*)d_in[13];
    const float* Wc     = (const float*)d_in[14];
    const float* bc     = (const float*)d_in[15];
    float* out = (float*)d_out;

    const int N = in_sizes[0] / 9;
    const int E = in_sizes[1] / 2;
    const int G = out_size / 2;
    const int n2 = 2 * N;

    int warp_blocks = (N * 32 + 255) / 256;
    int TB = warp_blocks;
    int ES4 = (E + 3) / 4;
    int HB = (2 * ES4 + 255) / 256;
    int nb_scan = (n2 + SCAN_ELEMS - 1) / SCAN_ELEMS;

    transform_hist_kernel<<<TB + HB, 256>>>(x, W1, atts1, attd1,
                                            ei_s + E, ei_t + E, W2, N, E, TB);
    scan_kernel<<<nb_scan, 1024>>>(n2, nb_scan);
    scatter_kernel<<<(2 * E + 255) / 256, 256>>>(ei_s, ei_s + E, ei_t, ei_t + E, E, n2);
    aggregate_kernel<0><<<warp_blocks, 256>>>(b1, N);
    gemm_mma_kernel<<<(N + 127) / 128, 256>>>(atts2, attd2, N);
    aggregate_kernel<1><<<warp_blocks, 256>>>(b2, N);
    pool_kernel<<<G, 512>>>(batch, Wc, bc, out, N);
}

// round 16
// speedup vs baseline: 1.0657x; 1.0657x over previous
#include <cuda_runtime.h>
#include <cuda_bf16.h>
#include <math.h>
#include <stdint.h>

// ---------------------------------------------------------------------------
// TrajectoryGAT: 2x GATConv + mean pool + linear + log_softmax
//   N=100000, E=1600000/layer, HID=128, G=256, OUT=2
//
// R16 = R14 (best, 288.8us) + one micro-opt:
//   - aggregate broadcasts precomputed BYTE OFFSETS (src*256) through the
//     shfl instead of node indices, deleting the IMAD.WIDE address multiply
//     from the serial dependent chain (ALU was the busiest pipe at 34%).
// The 2-edges/iter family (R8, R15) is abandoned: both regressed (L1-bound).
// ---------------------------------------------------------------------------

#define NN 100000
#define EE 1600000
#define HID 128
#define SCAN_ELEMS 2048

// ---- device scratch ----
__device__ __align__(16) uint2    g_hb[(size_t)NN * 32];    // h (bf16) gathers
__device__ __align__(16) uint2    g_ab[(size_t)NN * 32];    // layer-1 out bf16 = GEMM A
__device__ __align__(16) float    g_acc[(size_t)NN * HID];  // layer-2 out fp32
__device__ float    g_as[NN];
__device__ float    g_ad[NN];
__device__ __align__(16) int g_cnt[2 * NN];
__device__ int      g_rowc[2 * NN + 1];
__device__ int      g_cur[2 * NN];
__device__ int      g_csrc[2 * EE];
__device__ __align__(16) unsigned g_w2b[64 * HID];          // W2 bf16x2 [k][n]
// lookback state (zero at entry; scatter re-zeroes)
__device__ int      g_ticket;
__device__ int      g_bflag[128];
__device__ int      g_bagg[128];
__device__ int      g_binc[128];

__device__ __forceinline__ uint2 pack4bf(float a, float b, float c, float d) {
    uint2 r;
    __nv_bfloat162 p0 = __float22bfloat162_rn(make_float2(a, b));
    __nv_bfloat162 p1 = __float22bfloat162_rn(make_float2(c, d));
    r.x = *(unsigned*)&p0;
    r.y = *(unsigned*)&p1;
    return r;
}

__device__ __forceinline__ float4 unpack4bf(uint2 v) {
    float2 f0 = __bfloat1622float2(*(__nv_bfloat162*)&v.x);
    float2 f1 = __bfloat1622float2(*(__nv_bfloat162*)&v.y);
    return make_float4(f0.x, f0.y, f1.x, f1.y);
}

// ---------------------------------------------------------------------------
// Fused: layer-1 transform (+ dots + W2 convert) || both histograms.
__global__ void transform_hist_kernel(const float* __restrict__ x, const float* __restrict__ W,
                                      const float* __restrict__ atts, const float* __restrict__ attd,
                                      const int* __restrict__ dst_s, const int* __restrict__ dst_t,
                                      const float* __restrict__ W2, int N, int E, int TB) {
    if ((int)blockIdx.x < TB) {
        int gid = blockIdx.x * 256 + threadIdx.x;
        if (gid < 64 * HID) {
            float2 v = *(const float2*)(W2 + gid * 2);
            __nv_bfloat162 p = __float22bfloat162_rn(v);
            g_w2b[gid] = *(unsigned*)&p;
        }
        int node = gid >> 5;
        int lane = threadIdx.x & 31;
        if (node >= N) return;
        float xv = (lane < 9) ? x[(size_t)node * 9 + lane] : 0.f;
        float4 acc = make_float4(0.f, 0.f, 0.f, 0.f);
#pragma unroll
        for (int k = 0; k < 9; k++) {
            float xk = __shfl_sync(0xffffffffu, xv, k);
            float4 w = *(const float4*)(W + k * HID + lane * 4);
            acc.x = fmaf(xk, w.x, acc.x);
            acc.y = fmaf(xk, w.y, acc.y);
            acc.z = fmaf(xk, w.z, acc.z);
            acc.w = fmaf(xk, w.w, acc.w);
        }
        g_hb[(size_t)node * 32 + lane] = pack4bf(acc.x, acc.y, acc.z, acc.w);
        float4 s4 = *(const float4*)(atts + lane * 4);
        float4 d4 = *(const float4*)(attd + lane * 4);
        float ps = acc.x * s4.x + acc.y * s4.y + acc.z * s4.z + acc.w * s4.w;
        float pd = acc.x * d4.x + acc.y * d4.y + acc.z * d4.z + acc.w * d4.w;
#pragma unroll
        for (int off = 16; off >= 1; off >>= 1) {
            ps += __shfl_xor_sync(0xffffffffu, ps, off);
            pd += __shfl_xor_sync(0xffffffffu, pd, off);
        }
        if (lane == 0) { g_as[node] = ps; g_ad[node] = pd; }
    } else {
        int ES4 = (E + 3) >> 2;
        int idx = (blockIdx.x - TB) * 256 + threadIdx.x;
        const int* dsa;
        int base, off0;
        if (idx < ES4)          { dsa = dst_s; base = idx * 4;         off0 = 0; }
        else if (idx < 2 * ES4) { dsa = dst_t; base = (idx - ES4) * 4; off0 = NN; }
        else return;
        if (base + 3 < E) {
            int4 d = *(const int4*)(dsa + base);
            atomicAdd(&g_cnt[off0 + d.x], 1);
            atomicAdd(&g_cnt[off0 + d.y], 1);
            atomicAdd(&g_cnt[off0 + d.z], 1);
            atomicAdd(&g_cnt[off0 + d.w], 1);
        } else {
            for (int j = base; j < E; ++j) atomicAdd(&g_cnt[off0 + dsa[j]], 1);
        }
    }
}

// ---------------------------------------------------------------------------
// Single-pass decoupled-lookback exclusive scan.
__global__ __launch_bounds__(1024) void scan_kernel(int n2, int nb) {
    __shared__ int sbid_sh, s_total, s_prefix;
    __shared__ int ws[32];
    int t = threadIdx.x, lane = t & 31, w = t >> 5;
    if (t == 0) sbid_sh = atomicAdd(&g_ticket, 1);
    __syncthreads();
    int bid = sbid_sh;
    int base = bid * SCAN_ELEMS;
    int i0 = base + t * 2;
    int2 v = make_int2(0, 0);
    if (i0 + 1 < n2) v = *(const int2*)&g_cnt[i0];
    else if (i0 < n2) v.x = g_cnt[i0];
    int local = v.x + v.y;
    int xv = local;
#pragma unroll
    for (int off = 1; off < 32; off <<= 1) {
        int u = __shfl_up_sync(0xffffffffu, xv, off);
        if (lane >= off) xv += u;
    }
    if (lane == 31) ws[w] = xv;
    __syncthreads();
    if (w == 0) {
        int s = ws[lane];
        int y = s;
#pragma unroll
        for (int off = 1; off < 32; off <<= 1) {
            int u = __shfl_up_sync(0xffffffffu, y, off);
            if (lane >= off) y += u;
        }
        ws[lane] = y - s;
        if (lane == 31) s_total = y;
    }
    __syncthreads();
    int thr_incl = xv + ws[w];
    int btotal = s_total;

    if (t == 0) {
        if (bid == 0) {
            g_binc[0] = btotal;
            __threadfence();
            atomicExch(&g_bflag[0], 2);
        } else {
            g_bagg[bid] = btotal;
            __threadfence();
            atomicExch(&g_bflag[bid], 1);
        }
    }
    if (t < 32) {
        int pre = 0;
        if (bid > 0) {
            int jbase = bid - 1;
            while (true) {
                int j = jbase - lane;
                int f = 0;
                if (j >= 0) {
                    do { f = atomicAdd(&g_bflag[j], 0); } while (f == 0);
                }
                int val = 0;
                if (j >= 0)
                    val = (f == 2) ? atomicAdd(&g_binc[j], 0) : atomicAdd(&g_bagg[j], 0);
                unsigned pm = __ballot_sync(0xffffffffu, j >= 0 && f == 2);
                if (pm) {
                    int fp = __ffs(pm) - 1;
                    int contrib = (lane <= fp) ? val : 0;
#pragma unroll
                    for (int off = 16; off >= 1; off >>= 1)
                        contrib += __shfl_xor_sync(0xffffffffu, contrib, off);
                    pre += contrib;
                    break;
                } else {
                    int contrib = val;
#pragma unroll
                    for (int off = 16; off >= 1; off >>= 1)
                        contrib += __shfl_xor_sync(0xffffffffu, contrib, off);
                    pre += contrib;
                    jbase -= 32;
                }
            }
            if (lane == 0) {
                g_binc[bid] = pre + btotal;
                __threadfence();
                atomicExch(&g_bflag[bid], 2);
            }
        }
        if (lane == 0) s_prefix = pre;
    }
    __syncthreads();
    int pfx = s_prefix;
    int excl = pfx + thr_incl - local;
    if (i0 < n2) { g_rowc[i0] = excl; g_cur[i0] = excl; }
    if (i0 + 1 < n2) { g_rowc[i0 + 1] = excl + v.x; g_cur[i0 + 1] = excl + v.x; }
    if (bid == nb - 1 && t == 0) g_rowc[n2] = pfx + btotal;
}

// ---------------------------------------------------------------------------
// Both scatters in one launch + state reset for next graph replay.
__global__ void scatter_kernel(const int* __restrict__ src_s, const int* __restrict__ dst_s,
                               const int* __restrict__ src_t, const int* __restrict__ dst_t,
                               int E, int n2) {
    int i = blockIdx.x * 256 + threadIdx.x;
    if (i < E) {
        int p = atomicAdd(&g_cur[dst_s[i]], 1);
        g_csrc[p] = src_s[i];
    } else if (i < 2 * E) {
        int k = i - E;
        int p = atomicAdd(&g_cur[NN + dst_t[k]], 1);
        g_csrc[p] = src_t[k];
    }
    if (i < n2) g_cnt[i] = 0;
    if (i < 128) g_bflag[i] = 0;
    if (i == 0) g_ticket = 0;
}

// ---------------------------------------------------------------------------
// Aggregation: one warp/dst, single pass (m=0 softmax). Parallel phase
// computes (byte_offset, w=exp(alpha)) for 32 edges; serial broadcast loop
// shfls the PRE-MULTIPLIED offset (no IMAD in the dependent chain).
template <int LAYER>
__global__ __launch_bounds__(256, 6) void aggregate_kernel(const float* __restrict__ bias, int n) {
    int node = (blockIdx.x * blockDim.x + threadIdx.x) >> 5;
    int lane = threadIdx.x & 31;
    if (node >= n) return;
    const int* rowb = g_rowc + LAYER * NN;
    int start = rowb[node], end = rowb[node + 1];
    float4 b = *(const float4*)(bias + lane * 4);

    if (start == end) {
        if (LAYER == 0) {
            float4 o = b;
            o.x = fmaxf(o.x, 0.f); o.y = fmaxf(o.y, 0.f);
            o.z = fmaxf(o.z, 0.f); o.w = fmaxf(o.w, 0.f);
            g_ab[(size_t)node * 32 + lane] = pack4bf(o.x, o.y, o.z, o.w);
        } else {
            *(float4*)(g_acc + (size_t)node * HID + lane * 4) = b;
        }
        return;
    }

    float ad = g_ad[node];
    float ssum = 0.f;
    float4 acc = make_float4(0.f, 0.f, 0.f, 0.f);
    const char* hlane = (const char*)g_hb + lane * 8;   // per-lane base
    for (int basei = start; basei < end; basei += 32) {
        int nloc = min(32, end - basei);
        int offl = 0;
        float wv = 0.f;
        if (lane < nloc) {
            int s = g_csrc[basei + lane];
            offl = s << 8;                   // byte offset of row (256 B)
            float a = g_as[s] + ad;
            a = fmaxf(a, 0.2f * a);          // leaky_relu(., 0.2)
            wv = __expf(fminf(a, 80.f));     // m=0; clamp guards overflow
        }
        ssum += wv;
#pragma unroll 8
        for (int t = 0; t < nloc; ++t) {
            int off = __shfl_sync(0xffffffffu, offl, t);
            float wt = __shfl_sync(0xffffffffu, wv, t);
            float4 hv = unpack4bf(*(const uint2*)(hlane + off));
            acc.x = fmaf(wt, hv.x, acc.x);
            acc.y = fmaf(wt, hv.y, acc.y);
            acc.z = fmaf(wt, hv.z, acc.z);
            acc.w = fmaf(wt, hv.w, acc.w);
        }
    }
#pragma unroll
    for (int off = 16; off >= 1; off >>= 1)
        ssum += __shfl_xor_sync(0xffffffffu, ssum, off);

    float inv = 1.f / (ssum + 1e-16f);
    float o0 = fmaf(acc.x, inv, b.x), o1 = fmaf(acc.y, inv, b.y);
    float o2 = fmaf(acc.z, inv, b.z), o3 = fmaf(acc.w, inv, b.w);
    if (LAYER == 0) {
        o0 = fmaxf(o0, 0.f); o1 = fmaxf(o1, 0.f);
        o2 = fmaxf(o2, 0.f); o3 = fmaxf(o3, 0.f);
        g_ab[(size_t)node * 32 + lane] = pack4bf(o0, o1, o2, o3);
    } else {
        *(float4*)(g_acc + (size_t)node * HID + lane * 4) = make_float4(o0, o1, o2, o3);
    }
}

// ---------------------------------------------------------------------------
// Tensor-core GEMM: h2[M,128] = g_ab(bf16) @ g_w2b, fp32 accum.
// Epilogue: bf16 store to g_hb + fused attention dots.
__global__ __launch_bounds__(256) void gemm_mma_kernel(const float* __restrict__ atts,
                                                       const float* __restrict__ attd, int M) {
    __shared__ __nv_bfloat16 As[128 * 72];
    __shared__ __nv_bfloat16 Bs[64 * 136];
    int tid = threadIdx.x;
    int lane = tid & 31, w = tid >> 5;
    int m0 = blockIdx.x * 128;
    float c[16][4];
#pragma unroll
    for (int i = 0; i < 16; i++)
#pragma unroll
        for (int j = 0; j < 4; j++) c[i][j] = 0.f;

    const char* abase = (const char*)g_ab;
    const char* bbase = (const char*)g_w2b;
    int grp = lane >> 3;
    int mw = w * 16;

    for (int ks = 0; ks < 2; ++ks) {
#pragma unroll
        for (int it = 0; it < 4; ++it) {
            int idx = tid + it * 256;
            int r = idx >> 3, c8 = idx & 7;
            uint4 v = make_uint4(0, 0, 0, 0);
            if (m0 + r < M)
                v = *(const uint4*)(abase + (size_t)(m0 + r) * 256 + ks * 128 + c8 * 16);
            *(uint4*)((char*)As + r * 144 + c8 * 16) = v;
        }
#pragma unroll
        for (int it = 0; it < 4; ++it) {
            int idx = tid + it * 256;
            int r = idx >> 4, c16 = idx & 15;
            uint4 v = *(const uint4*)(bbase + (size_t)(ks * 64 + r) * 256 + c16 * 16);
            *(uint4*)((char*)Bs + r * 272 + c16 * 16) = v;
        }
        __syncthreads();

#pragma unroll
        for (int kk = 0; kk < 64; kk += 16) {
            int arow = mw + (lane & 7) + (grp & 1) * 8;
            int acol = kk + (grp >> 1) * 8;
            uint32_t aaddr = (uint32_t)__cvta_generic_to_shared(As) + arow * 144 + acol * 2;
            uint32_t a0, a1, a2, a3;
            asm volatile("ldmatrix.sync.aligned.m8n8.x4.shared.b16 {%0,%1,%2,%3}, [%4];"
                         : "=r"(a0), "=r"(a1), "=r"(a2), "=r"(a3) : "r"(aaddr));
#pragma unroll
            for (int np = 0; np < 8; ++np) {
                int brow = kk + (lane & 7) + (grp & 1) * 8;
                int bcol = np * 16 + (grp >> 1) * 8;
                uint32_t baddr = (uint32_t)__cvta_generic_to_shared(Bs) + brow * 272 + bcol * 2;
                uint32_t b0, b1, b2, b3;
                asm volatile("ldmatrix.sync.aligned.m8n8.x4.trans.shared.b16 {%0,%1,%2,%3}, [%4];"
                             : "=r"(b0), "=r"(b1), "=r"(b2), "=r"(b3) : "r"(baddr));
                asm volatile("mma.sync.aligned.m16n8k16.row.col.f32.bf16.bf16.f32 "
                             "{%0,%1,%2,%3}, {%4,%5,%6,%7}, {%8,%9}, {%0,%1,%2,%3};"
                             : "+f"(c[2 * np][0]), "+f"(c[2 * np][1]),
                               "+f"(c[2 * np][2]), "+f"(c[2 * np][3])
                             : "r"(a0), "r"(a1), "r"(a2), "r"(a3), "r"(b0), "r"(b1));
                asm volatile("mma.sync.aligned.m16n8k16.row.col.f32.bf16.bf16.f32 "
                             "{%0,%1,%2,%3}, {%4,%5,%6,%7}, {%8,%9}, {%0,%1,%2,%3};"
                             : "+f"(c[2 * np + 1][0]), "+f"(c[2 * np + 1][1]),
                               "+f"(c[2 * np + 1][2]), "+f"(c[2 * np + 1][3])
                             : "r"(a0), "r"(a1), "r"(a2), "r"(a3), "r"(b2), "r"(b3));
            }
        }
        __syncthreads();
    }

    int r = lane >> 2, q = lane & 3;
    int row1 = m0 + mw + r, row2 = row1 + 8;
    unsigned* hb32 = (unsigned*)g_hb;
    float ps1 = 0.f, pd1 = 0.f, ps2 = 0.f, pd2 = 0.f;
#pragma unroll
    for (int nt = 0; nt < 16; ++nt) {
        int col = nt * 8 + q * 2;
        float2 sa = *(const float2*)(atts + col);
        float2 da = *(const float2*)(attd + col);
        ps1 += c[nt][0] * sa.x + c[nt][1] * sa.y;
        pd1 += c[nt][0] * da.x + c[nt][1] * da.y;
        ps2 += c[nt][2] * sa.x + c[nt][3] * sa.y;
        pd2 += c[nt][2] * da.x + c[nt][3] * da.y;
        if (row1 < M) {
            __nv_bfloat162 p = __float22bfloat162_rn(make_float2(c[nt][0], c[nt][1]));
            hb32[(size_t)row1 * 64 + nt * 4 + q] = *(unsigned*)&p;
        }
        if (row2 < M) {
            __nv_bfloat162 p = __float22bfloat162_rn(make_float2(c[nt][2], c[nt][3]));
            hb32[(size_t)row2 * 64 + nt * 4 + q] = *(unsigned*)&p;
        }
    }
#pragma unroll
    for (int off = 1; off <= 2; off <<= 1) {
        ps1 += __shfl_xor_sync(0xffffffffu, ps1, off);
        pd1 += __shfl_xor_sync(0xffffffffu, pd1, off);
        ps2 += __shfl_xor_sync(0xffffffffu, ps2, off);
        pd2 += __shfl_xor_sync(0xffffffffu, pd2, off);
    }
    if (q == 0) {
        if (row1 < M) { g_as[row1] = ps1; g_ad[row1] = pd1; }
        if (row2 < M) { g_as[row2] = ps2; g_ad[row2] = pd2; }
    }
}

// ---------------------------------------------------------------------------
__global__ __launch_bounds__(512) void pool_kernel(const int* __restrict__ batch,
                                                   const float* __restrict__ Wc,
                                                   const float* __restrict__ bc,
                                                   float* __restrict__ out, int N) {
    int g = blockIdx.x;
    int t = threadIdx.x;
    int c = t & 127;
    int part = t >> 7;
    int lo = 0, hi = N;
    while (lo < hi) { int mid = (lo + hi) >> 1; if (batch[mid] < g) lo = mid + 1; else hi = mid; }
    int start = lo;
    hi = N;
    while (lo < hi) { int mid = (lo + hi) >> 1; if (batch[mid] < g + 1) lo = mid + 1; else hi = mid; }
    int end = lo;

    float sum = 0.f;
    for (int nd = start + part; nd < end; nd += 4) sum += g_acc[(size_t)nd * HID + c];
    __shared__ float sh[512];
    sh[t] = sum;
    __syncthreads();
    if (t < 128) {
        float s = sh[t] + sh[t + 128] + sh[t + 256] + sh[t + 384];
        float cnt = (float)(end - start);
        if (cnt < 1.f) cnt = 1.f;
        float p = s / cnt;
        sh[t] = p * Wc[c * 2 + 0];
        sh[t + 128] = p * Wc[c * 2 + 1];
    }
    __syncthreads();
    for (int off = 64; off >= 1; off >>= 1) {
        if (t < off) { sh[t] += sh[t + off]; sh[128 + t] += sh[128 + t + off]; }
        __syncthreads();
    }
    if (t == 0) {
        float l0 = sh[0] + bc[0];
        float l1 = sh[128] + bc[1];
        float mx = fmaxf(l0, l1);
        float lse = mx + logf(expf(l0 - mx) + expf(l1 - mx));
        out[g * 2 + 0] = l0 - lse;
        out[g * 2 + 1] = l1 - lse;
    }
}

// ---------------------------------------------------------------------------
extern "C" void kernel_launch(void* const* d_in, const int* in_sizes, int n_in,
                              void* d_out, int out_size) {
    const float* x      = (const float*)d_in[0];
    const int*   ei_s   = (const int*)d_in[1];
    const int*   ei_t   = (const int*)d_in[3];
    const int*   batch  = (const int*)d_in[5];
    const float* W1     = (const float*)d_in[6];
    const float* atts1  = (const float*)d_in[7];
    const float* attd1  = (const float*)d_in[8];
    const float* b1     = (const float*)d_in[9];
    const float* W2     = (const float*)d_in[10];
    const float* atts2  = (const float*)d_in[11];
    const float* attd2  = (const float*)d_in[12];
    const float* b2     = (const float*)d_in[13];
    const float* Wc     = (const float*)d_in[14];
    const float* bc     = (const float*)d_in[15];
    float* out = (float*)d_out;

    const int N = in_sizes[0] / 9;
    const int E = in_sizes[1] / 2;
    const int G = out_size / 2;
    const int n2 = 2 * N;

    int warp_blocks = (N * 32 + 255) / 256;
    int TB = warp_blocks;
    int ES4 = (E + 3) / 4;
    int HB = (2 * ES4 + 255) / 256;
    int nb_scan = (n2 + SCAN_ELEMS - 1) / SCAN_ELEMS;

    transform_hist_kernel<<<TB + HB, 256>>>(x, W1, atts1, attd1,
                                            ei_s + E, ei_t + E, W2, N, E, TB);
    scan_kernel<<<nb_scan, 1024>>>(n2, nb_scan);
    scatter_kernel<<<(2 * E + 255) / 256, 256>>>(ei_s, ei_s + E, ei_t, ei_t + E, E, n2);
    aggregate_kernel<0><<<warp_blocks, 256>>>(b1, N);
    gemm_mma_kernel<<<(N + 127) / 128, 256>>>(atts2, attd2, N);
    aggregate_kernel<1><<<warp_blocks, 256>>>(b2, N);
    pool_kernel<<<G, 512>>>(batch, Wc, bc, out, N);
}